// round 1
// baseline (speedup 1.0000x reference)
#include <cuda_runtime.h>

// Embedding gather: out[row, :] = weight[ids[row], :]
// ids: [8192] int32 (flattened 4x2048), weight: [32000, 1024] f32,
// out: [8192, 1024] f32.
//
// One CTA per output row; 256 threads x float4 = 1024 floats = one row.
// Fully coalesced 128B transactions on both load and store.

#define DIM 1024
#define VEC (DIM / 4)   // 256 float4 per row

__global__ void __launch_bounds__(256, 8)
embed_gather_kernel(const int* __restrict__ ids,
                    const float* __restrict__ weight,
                    float* __restrict__ out)
{
    const int row = blockIdx.x;
    const int id  = __ldg(ids + row);

    const float4* __restrict__ src =
        reinterpret_cast<const float4*>(weight) + (size_t)id * VEC;
    float4* __restrict__ dst =
        reinterpret_cast<float4*>(out) + (size_t)row * VEC;

    dst[threadIdx.x] = __ldg(src + threadIdx.x);
}

extern "C" void kernel_launch(void* const* d_in, const int* in_sizes, int n_in,
                              void* d_out, int out_size)
{
    // metadata order: input_ids (int32, 4*2048), weight (float32, 32000*1024)
    const int*   ids    = (const int*)d_in[0];
    const float* weight = (const float*)d_in[1];
    float*       out    = (float*)d_out;

    const int n_rows = in_sizes[0];   // 8192

    embed_gather_kernel<<<n_rows, 256>>>(ids, weight, out);
}